// round 1
// baseline (speedup 1.0000x reference)
#include <cuda_runtime.h>
#include <cstdint>

// Problem constants (B=2, H=16, S=2048, D=128, fp32 in/out, int32 mask over keys)
constexpr int Bc = 2, Hh = 16, Ss = 2048, Dd = 128;
constexpr int BM = 64;          // queries per block
constexpr int BN = 64;          // keys per KV tile
constexpr int NTHREADS = 128;   // 4 warps, one per SMSP
constexpr int KSTRIDE = 132;    // smem row stride (words) for K  -> conflict-free LDS
constexpr int VSTRIDE = 136;    // smem row stride (words) for V  -> conflict-free LDS
constexpr float SCALE_F = 0.08838834764831845f;  // 1/sqrt(128)
constexpr float NEGF = -1000000000.0f;

// fp32 -> tf32 (round to nearest)
__device__ __forceinline__ uint32_t f2tf(float x) {
    uint32_t r;
    asm("cvt.rna.tf32.f32 %0, %1;" : "=r"(r) : "f"(x));
    return r;
}

// D(16x8,f32) += A(16x8,tf32,row) * B(8x8,tf32,col)
__device__ __forceinline__ void mma8(float* d, uint32_t a0, uint32_t a1, uint32_t a2,
                                     uint32_t a3, uint32_t b0, uint32_t b1) {
    asm volatile(
        "mma.sync.aligned.m16n8k8.row.col.f32.tf32.tf32.f32 "
        "{%0,%1,%2,%3},{%4,%5,%6,%7},{%8,%9},{%0,%1,%2,%3};"
        : "+f"(d[0]), "+f"(d[1]), "+f"(d[2]), "+f"(d[3])
        : "r"(a0), "r"(a1), "r"(a2), "r"(a3), "r"(b0), "r"(b1));
}

__global__ void __launch_bounds__(NTHREADS, 1)
fa_tf32_kernel(const float* __restrict__ q, const float* __restrict__ k,
               const float* __restrict__ v, const int* __restrict__ mask,
               float* __restrict__ out) {
    extern __shared__ uint32_t smem[];
    uint32_t* sK = smem;                              // 64*132 words (tf32)
    uint32_t* sV = smem + BN * KSTRIDE;               // 64*136 words (tf32)
    float* sMask = (float*)(smem + BN * KSTRIDE + BN * VSTRIDE);  // 2048 words

    const int tid = threadIdx.x;
    const int warp = tid >> 5, lane = tid & 31;
    const int g = lane >> 2, tig = lane & 3;          // groupID, thread-in-group
    const int qb = blockIdx.x, bh = blockIdx.y;
    const int b = bh / Hh;

    const size_t bh_base = (size_t)bh * Ss * Dd;
    const float* qg = q + bh_base + (size_t)qb * BM * Dd;
    const float* kg = k + bh_base;
    const float* vg = v + bh_base;

    // Stage mask row for this batch (selector 1.0 / 0.0), once per block.
    for (int i = tid; i < Ss; i += NTHREADS)
        sMask[i] = (mask[b * Ss + i] != 0) ? 1.0f : 0.0f;

    // Stage Q (raw fp32) into the sK region, then pull A-fragments to registers.
    float* sQ = (float*)sK;
    for (int i = tid; i < BM * (Dd / 4); i += NTHREADS) {
        int r = i >> 5, c = (i & 31) * 4;
        float4 t4 = *(const float4*)(qg + (size_t)r * Dd + c);
        *(float4*)(sQ + r * KSTRIDE + c) = t4;
    }
    __syncthreads();

    const int r0 = warp * 16 + g;   // query row (within block) for acc rows 0/1
    const int r1 = r0 + 8;          // query row for acc rows 2/3

    uint32_t qf[16][4];             // Q A-fragments for all 16 k-steps (D=128)
#pragma unroll
    for (int kk = 0; kk < 16; kk++) {
        qf[kk][0] = f2tf(sQ[r0 * KSTRIDE + kk * 8 + tig]);
        qf[kk][1] = f2tf(sQ[r1 * KSTRIDE + kk * 8 + tig]);
        qf[kk][2] = f2tf(sQ[r0 * KSTRIDE + kk * 8 + tig + 4]);
        qf[kk][3] = f2tf(sQ[r1 * KSTRIDE + kk * 8 + tig + 4]);
    }

    float oa[16][4];                // O accumulator: 16 n-tiles x (2 rows x 2 cols)
#pragma unroll
    for (int n = 0; n < 16; n++)
        oa[n][0] = oa[n][1] = oa[n][2] = oa[n][3] = 0.f;
    float m0 = -1e30f, m1 = -1e30f, l0 = 0.f, l1 = 0.f;

#pragma unroll 1
    for (int t = 0; t < Ss / BN; t++) {
        const int n0 = t * BN;
        __syncthreads();  // all warps done with previous sK/sV (and Q extraction)

        // Stage K and V tiles as tf32 into padded smem.
        for (int i = tid; i < BN * (Dd / 4); i += NTHREADS) {
            int r = i >> 5, c = (i & 31) * 4;
            float4 t4 = *(const float4*)(kg + (size_t)(n0 + r) * Dd + c);
            uint4 u;
            u.x = f2tf(t4.x); u.y = f2tf(t4.y); u.z = f2tf(t4.z); u.w = f2tf(t4.w);
            *(uint4*)(sK + r * KSTRIDE + c) = u;
            float4 t5 = *(const float4*)(vg + (size_t)(n0 + r) * Dd + c);
            uint4 w;
            w.x = f2tf(t5.x); w.y = f2tf(t5.y); w.z = f2tf(t5.z); w.w = f2tf(t5.w);
            *(uint4*)(sV + r * VSTRIDE + c) = w;
        }
        __syncthreads();

        // ---- S = Q K^T (16 x 64 per warp) ----
        float sa[8][4];
#pragma unroll
        for (int j = 0; j < 8; j++)
            sa[j][0] = sa[j][1] = sa[j][2] = sa[j][3] = 0.f;
#pragma unroll
        for (int kk = 0; kk < 16; kk++) {
#pragma unroll
            for (int j = 0; j < 8; j++) {
                uint32_t b0 = sK[(j * 8 + g) * KSTRIDE + kk * 8 + tig];
                uint32_t b1 = sK[(j * 8 + g) * KSTRIDE + kk * 8 + tig + 4];
                mma8(sa[j], qf[kk][0], qf[kk][1], qf[kk][2], qf[kk][3], b0, b1);
            }
        }

        // ---- mask + scale + row max ----
        float mx0 = -1e30f, mx1 = -1e30f;
#pragma unroll
        for (int j = 0; j < 8; j++) {
            float sel0 = sMask[n0 + j * 8 + 2 * tig];
            float sel1 = sMask[n0 + j * 8 + 2 * tig + 1];
            sa[j][0] = (sel0 != 0.f) ? sa[j][0] * SCALE_F : NEGF;
            sa[j][1] = (sel1 != 0.f) ? sa[j][1] * SCALE_F : NEGF;
            sa[j][2] = (sel0 != 0.f) ? sa[j][2] * SCALE_F : NEGF;
            sa[j][3] = (sel1 != 0.f) ? sa[j][3] * SCALE_F : NEGF;
            mx0 = fmaxf(mx0, fmaxf(sa[j][0], sa[j][1]));
            mx1 = fmaxf(mx1, fmaxf(sa[j][2], sa[j][3]));
        }
        mx0 = fmaxf(mx0, __shfl_xor_sync(0xffffffffu, mx0, 1));
        mx0 = fmaxf(mx0, __shfl_xor_sync(0xffffffffu, mx0, 2));
        mx1 = fmaxf(mx1, __shfl_xor_sync(0xffffffffu, mx1, 1));
        mx1 = fmaxf(mx1, __shfl_xor_sync(0xffffffffu, mx1, 2));

        float mn0 = fmaxf(m0, mx0), mn1 = fmaxf(m1, mx1);
        float al0 = __expf(m0 - mn0), al1 = __expf(m1 - mn1);

        // ---- P = exp(S - m), row sums; store P back as tf32 bits in sa ----
        float rs0 = 0.f, rs1 = 0.f;
#pragma unroll
        for (int j = 0; j < 8; j++) {
            float p00 = __expf(sa[j][0] - mn0);
            float p01 = __expf(sa[j][1] - mn0);
            float p10 = __expf(sa[j][2] - mn1);
            float p11 = __expf(sa[j][3] - mn1);
            rs0 += p00 + p01;
            rs1 += p10 + p11;
            sa[j][0] = __uint_as_float(f2tf(p00));
            sa[j][1] = __uint_as_float(f2tf(p01));
            sa[j][2] = __uint_as_float(f2tf(p10));
            sa[j][3] = __uint_as_float(f2tf(p11));
        }
        rs0 += __shfl_xor_sync(0xffffffffu, rs0, 1);
        rs0 += __shfl_xor_sync(0xffffffffu, rs0, 2);
        rs1 += __shfl_xor_sync(0xffffffffu, rs1, 1);
        rs1 += __shfl_xor_sync(0xffffffffu, rs1, 2);
        l0 = l0 * al0 + rs0;
        l1 = l1 * al1 + rs1;
        m0 = mn0;
        m1 = mn1;

        // rescale O accumulator
#pragma unroll
        for (int n = 0; n < 16; n++) {
            oa[n][0] *= al0; oa[n][1] *= al0;
            oa[n][2] *= al1; oa[n][3] *= al1;
        }

        // ---- O += P V : convert P acc-layout -> A-fragment layout via shfl ----
#pragma unroll
        for (int kk = 0; kk < 8; kk++) {
            uint32_t c0 = __float_as_uint(sa[kk][0]);
            uint32_t c1 = __float_as_uint(sa[kk][1]);
            uint32_t c2 = __float_as_uint(sa[kk][2]);
            uint32_t c3 = __float_as_uint(sa[kk][3]);
            int src0 = (lane & 28) | (tig >> 1);  // col tig lives at t' = tig/2
            int src1 = src0 + 2;                  // col tig+4 lives at t' = tig/2+2
            uint32_t x0 = __shfl_sync(0xffffffffu, c0, src0);
            uint32_t x1 = __shfl_sync(0xffffffffu, c1, src0);
            uint32_t y0 = __shfl_sync(0xffffffffu, c0, src1);
            uint32_t y1 = __shfl_sync(0xffffffffu, c1, src1);
            uint32_t a0 = (tig & 1) ? x1 : x0;    // P[g][8kk+tig]
            uint32_t a2 = (tig & 1) ? y1 : y0;    // P[g][8kk+tig+4]
            x0 = __shfl_sync(0xffffffffu, c2, src0);
            x1 = __shfl_sync(0xffffffffu, c3, src0);
            y0 = __shfl_sync(0xffffffffu, c2, src1);
            y1 = __shfl_sync(0xffffffffu, c3, src1);
            uint32_t a1 = (tig & 1) ? x1 : x0;    // P[g+8][8kk+tig]
            uint32_t a3 = (tig & 1) ? y1 : y0;    // P[g+8][8kk+tig+4]
#pragma unroll
            for (int n = 0; n < 16; n++) {
                uint32_t b0 = sV[(kk * 8 + tig) * VSTRIDE + n * 8 + g];
                uint32_t b1 = sV[(kk * 8 + tig + 4) * VSTRIDE + n * 8 + g];
                mma8(oa[n], a0, a1, a2, a3, b0, b1);
            }
        }
    }

    // ---- epilogue: normalize and store ----
    float i0 = 1.f / l0, i1 = 1.f / l1;
    float* og = out + bh_base + (size_t)qb * BM * Dd;
#pragma unroll
    for (int n = 0; n < 16; n++) {
        int c = n * 8 + 2 * tig;
        float2 v0 = make_float2(oa[n][0] * i0, oa[n][1] * i0);
        float2 v1 = make_float2(oa[n][2] * i1, oa[n][3] * i1);
        *(float2*)(og + (size_t)r0 * Dd + c) = v0;
        *(float2*)(og + (size_t)r1 * Dd + c) = v1;
    }
}

extern "C" void kernel_launch(void* const* d_in, const int* in_sizes, int n_in,
                              void* d_out, int out_size) {
    (void)in_sizes; (void)n_in; (void)out_size;
    const float* q = (const float*)d_in[0];
    const float* k = (const float*)d_in[1];
    const float* v = (const float*)d_in[2];
    const int* mask = (const int*)d_in[3];
    float* out = (float*)d_out;

    constexpr int SMEM_BYTES = (BN * KSTRIDE + BN * VSTRIDE + Ss) * 4;  // 76800
    cudaFuncSetAttribute(fa_tf32_kernel, cudaFuncAttributeMaxDynamicSharedMemorySize,
                         SMEM_BYTES);
    dim3 grid(Ss / BM, Bc * Hh);
    fa_tf32_kernel<<<grid, NTHREADS, SMEM_BYTES>>>(q, k, v, mask, out);
}